// round 1
// baseline (speedup 1.0000x reference)
#include <cuda_runtime.h>

// CIN (xDeepFM) fused 3-layer kernel.
// B=4096, F0=39, D=16, H=128 per layer, Fi = {39,128,128}.
// out[b, l*128+h] = sum_d Z_l[b,h,d]
// Z_l[b,h,d] = b_l[h] + sum_j X0[b,j,d] * (sum_k W_l[h, j*Fi+k] * Xi[b,k,d])

#define THREADS 256
#define NB      4       // batches per block
#define HD      128
#define F0C     39
#define DD      16
#define DP      8       // 8 packed f32x2 pairs = 16 d values
#define ROWS    20      // smem row stride in floats (80B: 16B-aligned, conflict-friendly)

typedef unsigned long long u64;

// Transposed weights: WT[c*128 + h] = W[h*cin + c]
__device__ float WT0g[39 * 39 * 128];
__device__ float WT1g[39 * 128 * 128];
__device__ float WT2g[39 * 128 * 128];

__device__ __forceinline__ u64 pk1(float w) {
    u64 r; asm("mov.b64 %0, {%1, %1};" : "=l"(r) : "f"(w)); return r;
}
__device__ __forceinline__ void upk(u64 v, float &lo, float &hi) {
    asm("mov.b64 {%0, %1}, %2;" : "=f"(lo), "=f"(hi) : "l"(v));
}
__device__ __forceinline__ u64 fma2(u64 a, u64 b, u64 c) {
    u64 r; asm("fma.rn.f32x2 %0, %1, %2, %3;" : "=l"(r) : "l"(a), "l"(b), "l"(c));
    return r;
}

// -------------------- W transpose: [H, cin] -> [cin, H] --------------------
__global__ void transpose_w(const float* __restrict__ W, float* __restrict__ WT, int cin) {
    __shared__ float t[32][33];
    int cb = blockIdx.x * 32, hb = blockIdx.y * 32;
    int x = threadIdx.x, y = threadIdx.y;  // (32, 8)
    #pragma unroll
    for (int i = y; i < 32; i += 8) {
        int c = cb + x;
        if (c < cin) t[i][x] = W[(hb + i) * cin + c];
    }
    __syncthreads();
    #pragma unroll
    for (int i = y; i < 32; i += 8) {
        int c = cb + i;
        if (c < cin) WT[c * 128 + hb + x] = t[x][i];
    }
}

// -------------------- one CIN layer for one batch, 2 h-values --------------
// xi: smem [FI][ROWS] (current layer input), x0: smem [F0C][ROWS]
template <int FI>
__device__ __forceinline__ void cin_layer(
    const float* __restrict__ WT,    // [F0C*FI][128] transposed weights (gmem, L2-resident)
    const float* __restrict__ bias,  // [128]
    const float* xi,
    const float* x0,
    int hh,                          // 0..63 ; handles h = hh and hh+64
    u64* acc0, u64* acc1)
{
    u64 bb0 = pk1(__ldg(bias + hh));
    u64 bb1 = pk1(__ldg(bias + hh + 64));
    #pragma unroll
    for (int p = 0; p < DP; p++) { acc0[p] = bb0; acc1[p] = bb1; }

    const float* wp = WT + hh;
    for (int j = 0; j < F0C; j++) {
        u64 s0[DP], s1[DP];
        #pragma unroll
        for (int p = 0; p < DP; p++) { s0[p] = 0ull; s1[p] = 0ull; }

        const float* xr = xi;
        #pragma unroll 4
        for (int k = 0; k < FI; k++) {
            u64 w0 = pk1(__ldg(wp));        // coalesced 128B per half-warp-group
            u64 w1 = pk1(__ldg(wp + 64));
            wp += 128;
            // 16 d-values as 8 packed pairs; warp-uniform address -> smem broadcast
            const ulonglong2* x2 = (const ulonglong2*)xr;
            ulonglong2 a = x2[0], b = x2[1], c = x2[2], d = x2[3];
            u64 xv[DP] = { a.x, a.y, b.x, b.y, c.x, c.y, d.x, d.y };
            xr += ROWS;
            #pragma unroll
            for (int p = 0; p < DP; p++) {
                s0[p] = fma2(w0, xv[p], s0[p]);
                s1[p] = fma2(w1, xv[p], s1[p]);
            }
        }
        // acc += X0[j,:] * s
        const ulonglong2* x02 = (const ulonglong2*)(x0 + j * ROWS);
        ulonglong2 a = x02[0], b = x02[1], c = x02[2], d = x02[3];
        u64 xv[DP] = { a.x, a.y, b.x, b.y, c.x, c.y, d.x, d.y };
        #pragma unroll
        for (int p = 0; p < DP; p++) {
            acc0[p] = fma2(xv[p], s0[p], acc0[p]);
            acc1[p] = fma2(xv[p], s1[p], acc1[p]);
        }
    }
}

// store Z into smem row and return sum over d
__device__ __forceinline__ float store_sum(float* dst, const u64* acc) {
    float s = 0.f;
    u64* d8 = (u64*)dst;
    #pragma unroll
    for (int p = 0; p < DP; p++) {
        d8[p] = acc[p];
        float lo, hi; upk(acc[p], lo, hi);
        s += lo + hi;
    }
    return s;
}
__device__ __forceinline__ float sum_only(const u64* acc) {
    float s = 0.f;
    #pragma unroll
    for (int p = 0; p < DP; p++) {
        float lo, hi; upk(acc[p], lo, hi);
        s += lo + hi;
    }
    return s;
}

// -------------------- fused main kernel ------------------------------------
__global__ __launch_bounds__(THREADS)
void cin_main(const float* __restrict__ x,      // [B, 39, 16]
              const float* __restrict__ bias0,
              const float* __restrict__ bias1,
              const float* __restrict__ bias2,
              float* __restrict__ out)          // [B, 384]
{
    __shared__ __align__(16) float x0s[NB][F0C * ROWS];
    __shared__ __align__(16) float xis[NB][HD * ROWS];

    int tid = threadIdx.x;
    int bl  = tid >> 6;      // local batch 0..3 (uniform within each warp)
    int hh  = tid & 63;      // handles h = hh and hh+64
    int bbase = blockIdx.x * NB;

    // load X0 for NB batches (coalesced gmem read)
    for (int i = tid; i < NB * F0C * DD; i += THREADS) {
        int bb = i / (F0C * DD);
        int r  = i - bb * (F0C * DD);
        int f  = r >> 4;
        int d  = r & 15;
        x0s[bb][f * ROWS + d] = x[(bbase + bb) * (F0C * DD) + r];
    }
    __syncthreads();

    u64 acc0[DP], acc1[DP];
    float* orow = out + (size_t)(bbase + bl) * 384;
    const float* x0p = &x0s[bl][0];
    float* xip = &xis[bl][0];

    // ---- layer 0 (Xi = X0, Fi = 39) ----
    cin_layer<F0C>(WT0g, bias0, x0p, x0p, hh, acc0, acc1);
    orow[hh]      = store_sum(xip + hh * ROWS,        acc0);
    orow[hh + 64] = store_sum(xip + (hh + 64) * ROWS, acc1);
    __syncthreads();

    // ---- layer 1 (Fi = 128), in-place Xi update ----
    cin_layer<HD>(WT1g, bias1, xip, x0p, hh, acc0, acc1);
    __syncthreads();   // all reads of xis complete before overwriting
    orow[128 + hh]      = store_sum(xip + hh * ROWS,        acc0);
    orow[128 + hh + 64] = store_sum(xip + (hh + 64) * ROWS, acc1);
    __syncthreads();

    // ---- layer 2 (Fi = 128), output only ----
    cin_layer<HD>(WT2g, bias2, xip, x0p, hh, acc0, acc1);
    orow[256 + hh]      = sum_only(acc0);
    orow[256 + hh + 64] = sum_only(acc1);
}

// -------------------- launch -----------------------------------------------
extern "C" void kernel_launch(void* const* d_in, const int* in_sizes, int n_in,
                              void* d_out, int out_size) {
    const float* x  = (const float*)d_in[0];
    const float* W0 = (const float*)d_in[1];
    const float* b0 = (const float*)d_in[2];
    const float* W1 = (const float*)d_in[3];
    const float* b1 = (const float*)d_in[4];
    const float* W2 = (const float*)d_in[5];
    const float* b2 = (const float*)d_in[6];
    float* out = (float*)d_out;

    float *wt0, *wt1, *wt2;
    cudaGetSymbolAddress((void**)&wt0, WT0g);
    cudaGetSymbolAddress((void**)&wt1, WT1g);
    cudaGetSymbolAddress((void**)&wt2, WT2g);

    dim3 tb(32, 8);
    transpose_w<<<dim3((1521 + 31) / 32, 4), tb>>>(W0, wt0, 1521);
    transpose_w<<<dim3((4992 + 31) / 32, 4), tb>>>(W1, wt1, 4992);
    transpose_w<<<dim3((4992 + 31) / 32, 4), tb>>>(W2, wt2, 4992);

    cin_main<<<4096 / NB, THREADS>>>(x, b0, b1, b2, out);
}